// round 9
// baseline (speedup 1.0000x reference)
#include <cuda_runtime.h>
#include <stdint.h>

// ---------------------------------------------------------------------------
// PairLoss: result = ( sum_{gt<0.5} exp(p) * sum_{gt>0.5} exp(-p) - n_neg ) / 2
//
// HBM-bound streaming reduction. LDG path saturates at ~5.9 TB/s (in-flight
// bytes limited by per-warp MLP; batching LDGs backfires via L1tex queue).
// This version: per-thread cp.async.cg (LDGSTS) 2-stage prefetch into
// thread-private SMEM slots -> ~64KB in flight per SM, no block syncs in the
// main loop (thread i produces and consumes only s[stage][i]; per-thread
// commit_group/wait_group ordering; empty commit每iter keeps accounting
// uniform).
//
// Deterministic: static tile->block map, fixed lane mapping, fixed-order fp64
// final combine in last-arriving block. Graph-capturable, allocation-free.
// ---------------------------------------------------------------------------

#define NBLOCKS 592
#define NTHREADS 512
#define TILE_F4 512                    // float4 per array per stage (8 KB)
#define STAGES 2

__device__ double g_part[3 * NBLOCKS];
__device__ unsigned int g_done = 0;    // self-resetting arrival counter

// ---- helpers --------------------------------------------------------------

__device__ __forceinline__ uint32_t smem_u32(const void* p) {
    uint32_t a;
    asm("{ .reg .u64 t; cvta.to.shared.u64 t, %1; cvt.u32.u64 %0, t; }"
        : "=r"(a) : "l"(p));
    return a;
}

__device__ __forceinline__ void cp16(void* smem_dst, const void* gsrc) {
    asm volatile("cp.async.cg.shared.global [%0], [%1], 16;"
                 :: "r"(smem_u32(smem_dst)), "l"(gsrc) : "memory");
}

__device__ __forceinline__ void cp_commit() {
    asm volatile("cp.async.commit_group;" ::: "memory");
}

template <int N>
__device__ __forceinline__ void cp_wait() {
    asm volatile("cp.async.wait_group %0;" :: "n"(N) : "memory");
}

__device__ __forceinline__ void accum_one(float p, float g, float& s_neg,
                                          float& s_pos, float& cnt) {
    bool pos = g > 0.5f;
    float e = __expf(pos ? -p : p);
    if (pos) s_pos += e;
    else { s_neg += e; cnt += 1.0f; }
}

// Reduce three values across the block; results valid on (warp 0, lane 0).
template <typename T>
__device__ __forceinline__ void block_reduce3(T& a, T& b, T& c, T* sh) {
    int lane = threadIdx.x & 31;
    int warp = threadIdx.x >> 5;
    const int nw = NTHREADS / 32;

    #pragma unroll
    for (int off = 16; off > 0; off >>= 1) {
        a += __shfl_down_sync(0xffffffffu, a, off);
        b += __shfl_down_sync(0xffffffffu, b, off);
        c += __shfl_down_sync(0xffffffffu, c, off);
    }
    if (lane == 0) { sh[warp] = a; sh[nw + warp] = b; sh[2 * nw + warp] = c; }
    __syncthreads();
    if (warp == 0) {
        a = (lane < nw) ? sh[lane] : (T)0;
        b = (lane < nw) ? sh[nw + lane] : (T)0;
        c = (lane < nw) ? sh[2 * nw + lane] : (T)0;
        #pragma unroll
        for (int off = 16; off > 0; off >>= 1) {
            a += __shfl_down_sync(0xffffffffu, a, off);
            b += __shfl_down_sync(0xffffffffu, b, off);
            c += __shfl_down_sync(0xffffffffu, c, off);
        }
    }
}

__device__ __forceinline__ void epilogue(float s_neg, float s_pos, float cnt,
                                         float* __restrict__ out) {
    __shared__ float shf[3 * (NTHREADS / 32)];
    block_reduce3(s_neg, s_pos, cnt, shf);

    __shared__ bool s_last;
    if (threadIdx.x == 0) {
        g_part[blockIdx.x]               = (double)s_neg;
        g_part[NBLOCKS + blockIdx.x]     = (double)s_pos;
        g_part[2 * NBLOCKS + blockIdx.x] = (double)cnt;
        __threadfence();
        unsigned int prev = atomicAdd(&g_done, 1u);
        s_last = (prev == (unsigned int)(gridDim.x - 1));
    }
    __syncthreads();

    if (s_last) {
        __threadfence();  // acquire: all blocks' partials now visible
        double a = 0.0, b = 0.0, c = 0.0;
        for (int k = threadIdx.x; k < NBLOCKS; k += NTHREADS) {
            a += g_part[k];
            b += g_part[NBLOCKS + k];
            c += g_part[2 * NBLOCKS + k];
        }
        __shared__ double shd[3 * (NTHREADS / 32)];
        block_reduce3(a, b, c, shd);
        if (threadIdx.x == 0) {
            out[0] = (float)((a * b - c) * 0.5);
            g_done = 0;  // reset for next graph replay
        }
    }
}

// ---- main kernel: per-thread cp.async prefetch pipeline -------------------

__global__ void __launch_bounds__(NTHREADS)
pairloss_cpasync(const float4* __restrict__ p4, const float4* __restrict__ g4,
                 const float* __restrict__ pred, const float* __restrict__ gt,
                 int n, float* __restrict__ out) {
    __shared__ alignas(128) float4 s_p[STAGES][TILE_F4];
    __shared__ alignas(128) float4 s_g[STAGES][TILE_F4];

    const int tid = threadIdx.x;
    const int b = blockIdx.x;

    const int n4 = n >> 2;
    const int ntiles_tot = n4 / TILE_F4;
    // tiles for this block: b, b+NBLOCKS, ... (static, deterministic)
    const int my_nt = (b < ntiles_tot) ? (ntiles_tot - b + NBLOCKS - 1) / NBLOCKS
                                       : 0;

    // prologue: each thread prefetches its own float4 of stages 0..STAGES-1
    #pragma unroll
    for (int t = 0; t < STAGES; t++) {
        if (t < my_nt) {
            size_t base = (size_t)(b + t * NBLOCKS) * TILE_F4 + tid;
            cp16(&s_p[t][tid], p4 + base);
            cp16(&s_g[t][tid], g4 + base);
        }
        cp_commit();   // one group per stage (possibly empty)
    }

    float s_neg = 0.0f, s_pos = 0.0f, cnt = 0.0f;

    for (int t = 0; t < my_nt; t++) {
        int st = t & 1;
        // groups complete in order; <=1 pending leaves only tile t+1's group
        cp_wait<1>();

        float4 p = s_p[st][tid];
        float4 g = s_g[st][tid];
        accum_one(p.x, g.x, s_neg, s_pos, cnt);
        accum_one(p.y, g.y, s_neg, s_pos, cnt);
        accum_one(p.z, g.z, s_neg, s_pos, cnt);
        accum_one(p.w, g.w, s_neg, s_pos, cnt);

        // refill this thread's slot for tile t+STAGES (WAR vs the LDS above is
        // separated by full global-load latency; slot is thread-private)
        int nt_ = t + STAGES;
        if (nt_ < my_nt) {
            size_t base = (size_t)(b + nt_ * NBLOCKS) * TILE_F4 + tid;
            cp16(&s_p[st][tid], p4 + base);
            cp16(&s_g[st][tid], g4 + base);
        }
        cp_commit();   // unconditional: keeps group count uniform
    }

    // remainder (float4s beyond full tiles + scalar tail): block 0 via LDG
    if (b == 0) {
        for (int i = ntiles_tot * TILE_F4 + tid; i < n4; i += NTHREADS) {
            float4 p = p4[i];
            float4 g = g4[i];
            accum_one(p.x, g.x, s_neg, s_pos, cnt);
            accum_one(p.y, g.y, s_neg, s_pos, cnt);
            accum_one(p.z, g.z, s_neg, s_pos, cnt);
            accum_one(p.w, g.w, s_neg, s_pos, cnt);
        }
        for (int i = (n4 << 2) + tid; i < n; i += NTHREADS)
            accum_one(pred[i], gt[i], s_neg, s_pos, cnt);
    }

    epilogue(s_neg, s_pos, cnt, out);
}

// Scalar fallback for unaligned inputs (not expected from the harness).
__global__ void __launch_bounds__(NTHREADS)
pairloss_scalar(const float* __restrict__ pred, const float* __restrict__ gt,
                int n, float* __restrict__ out) {
    float s_neg = 0.0f, s_pos = 0.0f, cnt = 0.0f;
    int stride = gridDim.x * blockDim.x;
    for (int i = blockIdx.x * blockDim.x + threadIdx.x; i < n; i += stride)
        accum_one(pred[i], gt[i], s_neg, s_pos, cnt);
    epilogue(s_neg, s_pos, cnt, out);
}

extern "C" void kernel_launch(void* const* d_in, const int* in_sizes, int n_in,
                              void* d_out, int out_size) {
    const float* pred = (const float*)d_in[0];
    const float* gt   = (const float*)d_in[1];
    float* out = (float*)d_out;
    int n = in_sizes[0];

    bool aligned = (((uintptr_t)pred | (uintptr_t)gt) & 0xF) == 0;
    if (aligned) {
        pairloss_cpasync<<<NBLOCKS, NTHREADS>>>(
            (const float4*)pred, (const float4*)gt, pred, gt, n, out);
    } else {
        pairloss_scalar<<<NBLOCKS, NTHREADS>>>(pred, gt, n, out);
    }
}